// round 2
// baseline (speedup 1.0000x reference)
#include <cuda_runtime.h>
#include <math.h>

#define T      2048
#define H      1024
#define EEMB   256
#define G3     3072     // 3 live gates (i, g, o) * H
#define NB     128      // persistent CTAs (1 per SM, GB300 has 152 SMs)
#define NT     1024

// ---------------- device scratch (no cudaMalloc allowed) ----------------
__device__ float g_pre[T * G3];        // hoisted input projection + biases  (25 MB)
__device__ float g_Wc[EEMB * H];       // W_map @ W_lin
__device__ float g_u[G3];              // W_e @ rowsum(W_map)
__device__ float g_v[G3];              // W_e @ (W_map@b_lin + b_map)
__device__ float g_rs[EEMB];
__device__ float g_q[EEMB];
__device__ float g_h1[H];
__device__ float g_h2[H];
__device__ float g_e0[EEMB];
__device__ float g_psum[NB];           // per-CTA exp-sum partials (deterministic)
__device__ unsigned g_barcnt;
__device__ unsigned g_bargen;

__device__ __forceinline__ float sigf(float x) { return 1.f / (1.f + expf(-x)); }
__device__ __forceinline__ int gate_row(int gate, int h) {
    // gates i, g, o -> PyTorch rows [0,H), [2H,3H), [3H,4H)
    return (gate == 0 ? 0 : (gate == 1 ? 2048 : 3072)) + h;
}

// ---------------- grid barrier (sense via monotonic generation) ----------------
__device__ __forceinline__ void grid_bar(unsigned target) {
    __syncthreads();
    if (threadIdx.x == 0) {
        __threadfence();
        unsigned old = atomicAdd(&g_barcnt, 1u);
        if (old == NB - 1) {
            atomicExch(&g_barcnt, 0u);
            __threadfence();
            atomicExch(&g_bargen, target);
        } else {
            while (*(volatile unsigned*)&g_bargen < target) {}
        }
        __threadfence();
    }
    __syncthreads();
}

__global__ void init_sync() { g_barcnt = 0u; g_bargen = 0u; }

// ---------------- pre-GEMM: pre[t, gate*H+h] = x[t,:] . W_ih1[row,:1024] + b ----
// C[2048, 3072] = A[2048,1024] @ B^T, B rows gathered from W_ih1 (stride 1280)
__global__ void __launch_bounds__(256) pre_gemm(
    const float* __restrict__ A, const float* __restrict__ W1,
    const float* __restrict__ b_ih1, const float* __restrict__ b_hh1)
{
    __shared__ float As[16][128];
    __shared__ float Bs[16][128];
    const int tid = threadIdx.x;
    const int m0 = blockIdx.y * 128, n0 = blockIdx.x * 128;
    const int lrow = tid >> 1;
    const int lk = (tid & 1) * 8;
    const float* Ap = A + (m0 + lrow) * 1024 + lk;
    const int ncol = n0 + lrow;
    const int orig = ncol < 1024 ? ncol : ncol + 1024;
    const float* Bp = W1 + orig * 1280 + lk;
    const int tx = tid & 15, ty = tid >> 4;

    float acc[8][8];
#pragma unroll
    for (int i = 0; i < 8; i++)
#pragma unroll
        for (int j = 0; j < 8; j++) acc[i][j] = 0.f;

    for (int kt = 0; kt < 1024; kt += 16) {
        float4 a0 = *(const float4*)(Ap + kt);
        float4 a1 = *(const float4*)(Ap + kt + 4);
        float4 b0 = *(const float4*)(Bp + kt);
        float4 b1 = *(const float4*)(Bp + kt + 4);
        __syncthreads();
        As[lk + 0][lrow] = a0.x; As[lk + 1][lrow] = a0.y;
        As[lk + 2][lrow] = a0.z; As[lk + 3][lrow] = a0.w;
        As[lk + 4][lrow] = a1.x; As[lk + 5][lrow] = a1.y;
        As[lk + 6][lrow] = a1.z; As[lk + 7][lrow] = a1.w;
        Bs[lk + 0][lrow] = b0.x; Bs[lk + 1][lrow] = b0.y;
        Bs[lk + 2][lrow] = b0.z; Bs[lk + 3][lrow] = b0.w;
        Bs[lk + 4][lrow] = b1.x; Bs[lk + 5][lrow] = b1.y;
        Bs[lk + 6][lrow] = b1.z; Bs[lk + 7][lrow] = b1.w;
        __syncthreads();
#pragma unroll
        for (int k = 0; k < 16; k++) {
            float ar[8], br[8];
            *(float4*)(ar)     = *(const float4*)(&As[k][ty * 8]);
            *(float4*)(ar + 4) = *(const float4*)(&As[k][ty * 8 + 4]);
            *(float4*)(br)     = *(const float4*)(&Bs[k][tx * 8]);
            *(float4*)(br + 4) = *(const float4*)(&Bs[k][tx * 8 + 4]);
#pragma unroll
            for (int i = 0; i < 8; i++)
#pragma unroll
                for (int j = 0; j < 8; j++) acc[i][j] += ar[i] * br[j];
        }
    }
#pragma unroll
    for (int j = 0; j < 8; j++) {
        const int n = n0 + tx * 8 + j;
        const int o = n < 1024 ? n : n + 1024;
        const float bias = b_ih1[o] + b_hh1[o];
#pragma unroll
        for (int i = 0; i < 8; i++)
            g_pre[(m0 + ty * 8 + i) * G3 + n] = acc[i][j] + bias;
    }
}

// ---------------- Wc = W_map[256,1024] @ W_lin[1024,1024] ----------------
__global__ void __launch_bounds__(256) wc_gemm(
    const float* __restrict__ Wmap, const float* __restrict__ Wlin)
{
    __shared__ float As[16][64];
    __shared__ float Bs[16][64];
    const int tid = threadIdx.x;
    const int m0 = blockIdx.y * 64, n0 = blockIdx.x * 64;
    const int arow = tid >> 2, ak = (tid & 3) * 4;
    const int bk = tid >> 4, bn = (tid & 15) * 4;
    const int tx = tid & 15, ty = tid >> 4;

    float acc[4][4];
#pragma unroll
    for (int i = 0; i < 4; i++)
#pragma unroll
        for (int j = 0; j < 4; j++) acc[i][j] = 0.f;

    for (int kt = 0; kt < 1024; kt += 16) {
        float4 av = *(const float4*)(Wmap + (m0 + arow) * 1024 + kt + ak);
        float4 bv = *(const float4*)(Wlin + (kt + bk) * 1024 + n0 + bn);
        __syncthreads();
        As[ak + 0][arow] = av.x; As[ak + 1][arow] = av.y;
        As[ak + 2][arow] = av.z; As[ak + 3][arow] = av.w;
        *(float4*)(&Bs[bk][bn]) = bv;
        __syncthreads();
#pragma unroll
        for (int k = 0; k < 16; k++) {
            float4 a = *(const float4*)(&As[k][ty * 4]);
            float4 b = *(const float4*)(&Bs[k][tx * 4]);
            float ar[4] = {a.x, a.y, a.z, a.w};
            float br[4] = {b.x, b.y, b.z, b.w};
#pragma unroll
            for (int i = 0; i < 4; i++)
#pragma unroll
                for (int j = 0; j < 4; j++) acc[i][j] += ar[i] * br[j];
        }
    }
#pragma unroll
    for (int i = 0; i < 4; i++)
#pragma unroll
        for (int j = 0; j < 4; j++)
            g_Wc[(m0 + ty * 4 + i) * 1024 + (n0 + tx * 4 + j)] = acc[i][j];
}

// ---------------- rs[e] = sum_o Wmap[e,o];  q[e] = Wmap[e,:]@b_lin + b_map[e] ----
__global__ void __launch_bounds__(256) precompute_q_rs(
    const float* __restrict__ Wmap, const float* __restrict__ blin,
    const float* __restrict__ bmap)
{
    const int e = blockIdx.x;
    const int tid = threadIdx.x;
    float rs = 0.f, p = 0.f;
    for (int o = tid; o < 1024; o += 256) {
        float w = Wmap[e * 1024 + o];
        rs += w; p += w * blin[o];
    }
#pragma unroll
    for (int off = 16; off; off >>= 1) {
        rs += __shfl_xor_sync(0xffffffffu, rs, off);
        p  += __shfl_xor_sync(0xffffffffu, p, off);
    }
    __shared__ float srs[8], sp[8];
    if ((tid & 31) == 0) { srs[tid >> 5] = rs; sp[tid >> 5] = p; }
    __syncthreads();
    if (tid == 0) {
        float R = 0.f, P = 0.f;
        for (int i = 0; i < 8; i++) { R += srs[i]; P += sp[i]; }
        g_rs[e] = R;
        g_q[e] = P + bmap[e];
    }
}

// ---------------- u[g'] = W_e[g',:]@rs ; v[g'] = W_e[g',:]@q ----------------
__global__ void __launch_bounds__(256) precompute_uv(const float* __restrict__ W1)
{
    const int wid = threadIdx.x >> 5, lane = threadIdx.x & 31;
    const int gp = blockIdx.x * 8 + wid;          // 0..3071
    const int gate = gp >> 10, h = gp & 1023;
    const int orig = gate_row(gate, h);
    const float* w = W1 + orig * 1280 + 1024;
    float us = 0.f, vs = 0.f;
    for (int e = lane; e < EEMB; e += 32) {
        float ww = w[e];
        us += ww * g_rs[e];
        vs += ww * g_q[e];
    }
#pragma unroll
    for (int off = 16; off; off >>= 1) {
        us += __shfl_xor_sync(0xffffffffu, us, off);
        vs += __shfl_xor_sync(0xffffffffu, vs, off);
    }
    if (lane == 0) { g_u[gp] = us; g_v[gp] = vs; }
}

// ---------------- persistent sequential kernel ----------------
// SMEM layout (floats):
#define SM_W2    0                     // [24][1024]  W_ih2 slices (u*3+gate rows)
#define SM_WE    24576                 // [24][256]   W_e slices
#define SM_WL    30720                 // [8][1024]   W_lin rows
#define SM_WC    38912                 // [2][1024]   Wc rows
#define SM_VEC   40960                 // [1024]      h1/h2 staging
#define SM_E0    41984                 // [256]
#define SM_RED   42240                 // [128]       psum staging
#define SM_GATE  42368                 // [24]
#define SM_B2    42392                 // [24]
#define SM_U     42416                 // [24]
#define SM_V     42440                 // [24]
#define SM_BL    42464                 // [8]
#define SM_PRE   42472                 // [24]
#define SM_MISC  42496                 // [8]
#define SMEM_FLOATS 42504
#define SMEM_BYTES  (SMEM_FLOATS * 4)

__global__ void __launch_bounds__(NT, 1) lstm_seq(
    const float* __restrict__ W_ih1, const float* __restrict__ W_ih2,
    const float* __restrict__ b_ih2, const float* __restrict__ b_hh2,
    const float* __restrict__ W_lin, const float* __restrict__ b_lin,
    float* __restrict__ out)
{
    extern __shared__ float sm[];
    float* sW2   = sm + SM_W2;
    float* sWe   = sm + SM_WE;
    float* sWl   = sm + SM_WL;
    float* sWc   = sm + SM_WC;
    float* sVec  = sm + SM_VEC;
    float* sE0   = sm + SM_E0;
    float* sRed  = sm + SM_RED;
    float* sGate = sm + SM_GATE;
    float* sB2   = sm + SM_B2;
    float* sU    = sm + SM_U;
    float* sV    = sm + SM_V;
    float* sBl   = sm + SM_BL;
    float* sPre  = sm + SM_PRE;
    float* sMisc = sm + SM_MISC;

    const int b = blockIdx.x;
    const int tid = threadIdx.x;
    const int wid = tid >> 5, lane = tid & 31;
    const int h0 = b * 8;                 // this CTA owns hidden units h0..h0+7
    unsigned gen = 0;

    // -------- load weight slices into SMEM --------
    for (int idx = tid; idx < 24 * 1024; idx += NT) {
        int j = idx >> 10, k = idx & 1023;            // j = u*3 + gate
        int orig = gate_row(j % 3, h0 + j / 3);
        sW2[idx] = W_ih2[orig * 1024 + k];
    }
    for (int idx = tid; idx < 24 * 256; idx += NT) {
        int j = idx >> 8, e = idx & 255;
        int orig = gate_row(j % 3, h0 + j / 3);
        sWe[idx] = W_ih1[orig * 1280 + 1024 + e];
    }
    for (int idx = tid; idx < 8 * 1024; idx += NT) {
        int r = idx >> 10, k = idx & 1023;
        sWl[idx] = W_lin[(h0 + r) * 1024 + k];
    }
    for (int idx = tid; idx < 2 * 1024; idx += NT) {
        int r = idx >> 10, k = idx & 1023;
        sWc[idx] = g_Wc[(b * 2 + r) * 1024 + k];
    }
    if (tid < 24) {
        int j = tid;
        int orig = gate_row(j % 3, h0 + j / 3);
        sB2[j] = b_ih2[orig] + b_hh2[orig];
        int gp = (j % 3) * 1024 + h0 + j / 3;
        sU[j] = g_u[gp];
        sV[j] = g_v[gp];
        sPre[j] = g_pre[(j % 3) * 1024 + h0 + j / 3];   // t = 0 prefetch
    } else if (tid < 32) {
        sBl[tid - 24] = b_lin[h0 + tid - 24];
    }
    grid_bar(++gen);

    for (int t = 0; t < T; ++t) {
        // ================= Phase A: g1 = pre + W_e@e0 + v - lse*u ; h1 ==========
        if (t > 0) {
            if (tid < 256) sE0[tid] = g_e0[tid];
            else if (tid < 384) sRed[tid - 256] = g_psum[tid - 256];
        }
        __syncthreads();
        float acc = 0.f;
        if (wid < 24 && t > 0) {
            const float4* w4 = (const float4*)(sWe + (wid << 8));
            const float4* e4 = (const float4*)sE0;
#pragma unroll
            for (int i = 0; i < 2; i++) {
                float4 a = w4[lane + 32 * i];
                float4 x = e4[lane + 32 * i];
                acc += a.x * x.x + a.y * x.y + a.z * x.z + a.w * x.w;
            }
#pragma unroll
            for (int off = 16; off; off >>= 1)
                acc += __shfl_xor_sync(0xffffffffu, acc, off);
        }
        if (wid == 24 && t > 0) {
            float s = sRed[lane] + sRed[lane + 32] + sRed[lane + 64] + sRed[lane + 96];
#pragma unroll
            for (int off = 16; off; off >>= 1)
                s += __shfl_xor_sync(0xffffffffu, s, off);
            if (lane == 0) sMisc[0] = logf(s);
        }
        __syncthreads();
        if (wid < 24 && lane == 0) {
            float g1 = sPre[wid];
            if (t > 0) g1 += acc + sV[wid] - sMisc[0] * sU[wid];
            sGate[wid] = g1;
        }
        __syncthreads();
        if (tid < 8) {
            float gi = sGate[tid * 3 + 0];
            float gg = sGate[tid * 3 + 1];
            float go = sGate[tid * 3 + 2];
            float c = sigf(gi) * tanhf(gg);
            g_h1[h0 + tid] = sigf(go) * tanhf(c);
        }
        grid_bar(++gen);

        // ================= Phase B: g2 = W_ih2@h1 + b2 ; h2 =====================
        sVec[tid] = g_h1[tid];
        __syncthreads();
        if (wid < 24) {
            const float4* w4 = (const float4*)(sW2 + (wid << 10));
            const float4* x4 = (const float4*)sVec;
            float a2 = 0.f;
#pragma unroll
            for (int i = 0; i < 8; i++) {
                float4 a = w4[lane + 32 * i];
                float4 x = x4[lane + 32 * i];
                a2 += a.x * x.x + a.y * x.y + a.z * x.z + a.w * x.w;
            }
#pragma unroll
            for (int off = 16; off; off >>= 1)
                a2 += __shfl_xor_sync(0xffffffffu, a2, off);
            if (lane == 0) sGate[wid] = a2 + sB2[wid];
        }
        __syncthreads();
        if (tid < 8) {
            float gi = sGate[tid * 3 + 0];
            float gg = sGate[tid * 3 + 1];
            float go = sGate[tid * 3 + 2];
            float c = sigf(gi) * tanhf(gg);
            g_h2[h0 + tid] = sigf(go) * tanhf(c);
        }
        grid_bar(++gen);

        // ================= Phase C: y, e0 = Wc@h2, expsum partial ===============
        sVec[tid] = g_h2[tid];
        if (t + 1 < T && tid >= 512 && tid < 536) {
            int j = tid - 512;
            sPre[j] = g_pre[(t + 1) * G3 + (j % 3) * 1024 + h0 + j / 3];
        }
        __syncthreads();
        if (wid < 8) {
            const float4* w4 = (const float4*)(sWl + (wid << 10));
            const float4* x4 = (const float4*)sVec;
            float a2 = 0.f;
#pragma unroll
            for (int i = 0; i < 8; i++) {
                float4 a = w4[lane + 32 * i];
                float4 x = x4[lane + 32 * i];
                a2 += a.x * x.x + a.y * x.y + a.z * x.z + a.w * x.w;
            }
#pragma unroll
            for (int off = 16; off; off >>= 1)
                a2 += __shfl_xor_sync(0xffffffffu, a2, off);
            if (lane == 0) {
                float y = a2 + sBl[wid];
                out[t * 1024 + h0 + wid] = y;
                sGate[wid] = expf(y);
            }
        } else if (wid < 10) {
            const int r = wid - 8;
            const float4* w4 = (const float4*)(sWc + (r << 10));
            const float4* x4 = (const float4*)sVec;
            float a2 = 0.f;
#pragma unroll
            for (int i = 0; i < 8; i++) {
                float4 a = w4[lane + 32 * i];
                float4 x = x4[lane + 32 * i];
                a2 += a.x * x.x + a.y * x.y + a.z * x.z + a.w * x.w;
            }
#pragma unroll
            for (int off = 16; off; off >>= 1)
                a2 += __shfl_xor_sync(0xffffffffu, a2, off);
            if (lane == 0) g_e0[b * 2 + r] = a2;
        }
        __syncthreads();
        if (tid == 0) {
            float s = 0.f;
#pragma unroll
            for (int i = 0; i < 8; i++) s += sGate[i];
            g_psum[b] = s;       // fixed order -> deterministic
        }
        grid_bar(++gen);
    }
}

// ---------------- launch ----------------
extern "C" void kernel_launch(void* const* d_in, const int* in_sizes, int n_in,
                              void* d_out, int out_size)
{
    const float* x    = (const float*)d_in[0];
    const float* Wih1 = (const float*)d_in[1];
    const float* bih1 = (const float*)d_in[3];
    const float* bhh1 = (const float*)d_in[4];
    const float* Wih2 = (const float*)d_in[5];
    const float* bih2 = (const float*)d_in[7];
    const float* bhh2 = (const float*)d_in[8];
    const float* Wlin = (const float*)d_in[9];
    const float* blin = (const float*)d_in[10];
    const float* Wmap = (const float*)d_in[11];
    const float* bmap = (const float*)d_in[12];
    float* out = (float*)d_out;

    cudaFuncSetAttribute(lstm_seq, cudaFuncAttributeMaxDynamicSharedMemorySize,
                         SMEM_BYTES);

    init_sync<<<1, 1>>>();
    pre_gemm<<<dim3(G3 / 128, T / 128), 256>>>(x, Wih1, bih1, bhh1);
    wc_gemm<<<dim3(1024 / 64, 256 / 64), 256>>>(Wmap, Wlin);
    precompute_q_rs<<<256, 256>>>(Wmap, blin, bmap);
    precompute_uv<<<G3 / 8, 256>>>(Wih1);
    lstm_seq<<<NB, NT, SMEM_BYTES>>>(Wih1, Wih2, bih2, bhh2, Wlin, blin, out);
}

// round 3
// speedup vs baseline: 1.3460x; 1.3460x over previous
#include <cuda_runtime.h>
#include <math.h>

#define T      2048
#define H      1024
#define EEMB   256
#define G3     3072     // 3 live gates (i, g, o) * H
#define NB     128      // persistent CTAs (1 per SM)
#define NT     1024

// ---------------- device scratch (no cudaMalloc allowed) ----------------
__device__ float g_pre[T * G3];        // hoisted input projection + biases  (25 MB)
__device__ float g_Wc[EEMB * H];       // W_map @ W_lin
__device__ float g_u[G3];              // W_e @ rowsum(W_map)
__device__ float g_v[G3];              // W_e @ (W_map@b_lin + b_map)
__device__ float g_rs[EEMB];
__device__ float g_q[EEMB];
__device__ float g_h1[H];
__device__ float g_h2[H];
__device__ float g_e0[EEMB];
__device__ float g_psum[NB];           // per-CTA exp-sum partials (deterministic)
__device__ unsigned g_cnt;             // monotonic barrier counter

__device__ __forceinline__ float sigf(float x) { return 1.f / (1.f + expf(-x)); }
__device__ __forceinline__ int gate_row(int gate, int h) {
    // gates i, g, o -> PyTorch rows [0,H), [2H,3H), [3H,4H)
    return (gate == 0 ? 0 : (gate == 1 ? 2048 : 3072)) + h;
}

// ---------------- fast grid barrier: monotonic counter, acq/rel ----------------
// Arrival: fire-and-forget REDG with release (orders this CTA's prior global
// stores). Wait: single poller per CTA spins on ld.acquire (orders subsequent
// global loads). No fences, no resets, wrap-safe compare.
__device__ __forceinline__ void grid_bar(unsigned target) {
    __syncthreads();                       // all CTA threads' work done
    if (threadIdx.x == 0) {
        unsigned one = 1u;
        asm volatile("red.release.gpu.global.add.u32 [%0], %1;"
                     :: "l"(&g_cnt), "r"(one) : "memory");
        unsigned v;
        do {
            asm volatile("ld.acquire.gpu.global.u32 %0, [%1];"
                         : "=r"(v) : "l"(&g_cnt) : "memory");
        } while ((int)(v - target) < 0);
    }
    __syncthreads();                       // release all warps
}

__global__ void init_sync() { g_cnt = 0u; }

// ---------------- pre-GEMM: pre[t, gate*H+h] = x[t,:] . W_ih1[row,:1024] + b ----
__global__ void __launch_bounds__(256) pre_gemm(
    const float* __restrict__ A, const float* __restrict__ W1,
    const float* __restrict__ b_ih1, const float* __restrict__ b_hh1)
{
    __shared__ float As[16][128];
    __shared__ float Bs[16][128];
    const int tid = threadIdx.x;
    const int m0 = blockIdx.y * 128, n0 = blockIdx.x * 128;
    const int lrow = tid >> 1;
    const int lk = (tid & 1) * 8;
    const float* Ap = A + (m0 + lrow) * 1024 + lk;
    const int ncol = n0 + lrow;
    const int orig = ncol < 1024 ? ncol : ncol + 1024;
    const float* Bp = W1 + orig * 1280 + lk;
    const int tx = tid & 15, ty = tid >> 4;

    float acc[8][8];
#pragma unroll
    for (int i = 0; i < 8; i++)
#pragma unroll
        for (int j = 0; j < 8; j++) acc[i][j] = 0.f;

    for (int kt = 0; kt < 1024; kt += 16) {
        float4 a0 = *(const float4*)(Ap + kt);
        float4 a1 = *(const float4*)(Ap + kt + 4);
        float4 b0 = *(const float4*)(Bp + kt);
        float4 b1 = *(const float4*)(Bp + kt + 4);
        __syncthreads();
        As[lk + 0][lrow] = a0.x; As[lk + 1][lrow] = a0.y;
        As[lk + 2][lrow] = a0.z; As[lk + 3][lrow] = a0.w;
        As[lk + 4][lrow] = a1.x; As[lk + 5][lrow] = a1.y;
        As[lk + 6][lrow] = a1.z; As[lk + 7][lrow] = a1.w;
        Bs[lk + 0][lrow] = b0.x; Bs[lk + 1][lrow] = b0.y;
        Bs[lk + 2][lrow] = b0.z; Bs[lk + 3][lrow] = b0.w;
        Bs[lk + 4][lrow] = b1.x; Bs[lk + 5][lrow] = b1.y;
        Bs[lk + 6][lrow] = b1.z; Bs[lk + 7][lrow] = b1.w;
        __syncthreads();
#pragma unroll
        for (int k = 0; k < 16; k++) {
            float ar[8], br[8];
            *(float4*)(ar)     = *(const float4*)(&As[k][ty * 8]);
            *(float4*)(ar + 4) = *(const float4*)(&As[k][ty * 8 + 4]);
            *(float4*)(br)     = *(const float4*)(&Bs[k][tx * 8]);
            *(float4*)(br + 4) = *(const float4*)(&Bs[k][tx * 8 + 4]);
#pragma unroll
            for (int i = 0; i < 8; i++)
#pragma unroll
                for (int j = 0; j < 8; j++) acc[i][j] += ar[i] * br[j];
        }
    }
#pragma unroll
    for (int j = 0; j < 8; j++) {
        const int n = n0 + tx * 8 + j;
        const int o = n < 1024 ? n : n + 1024;
        const float bias = b_ih1[o] + b_hh1[o];
#pragma unroll
        for (int i = 0; i < 8; i++)
            g_pre[(m0 + ty * 8 + i) * G3 + n] = acc[i][j] + bias;
    }
}

// ---------------- Wc = W_map[256,1024] @ W_lin[1024,1024] ----------------
__global__ void __launch_bounds__(256) wc_gemm(
    const float* __restrict__ Wmap, const float* __restrict__ Wlin)
{
    __shared__ float As[16][64];
    __shared__ float Bs[16][64];
    const int tid = threadIdx.x;
    const int m0 = blockIdx.y * 64, n0 = blockIdx.x * 64;
    const int arow = tid >> 2, ak = (tid & 3) * 4;
    const int bk = tid >> 4, bn = (tid & 15) * 4;
    const int tx = tid & 15, ty = tid >> 4;

    float acc[4][4];
#pragma unroll
    for (int i = 0; i < 4; i++)
#pragma unroll
        for (int j = 0; j < 4; j++) acc[i][j] = 0.f;

    for (int kt = 0; kt < 1024; kt += 16) {
        float4 av = *(const float4*)(Wmap + (m0 + arow) * 1024 + kt + ak);
        float4 bv = *(const float4*)(Wlin + (kt + bk) * 1024 + n0 + bn);
        __syncthreads();
        As[ak + 0][arow] = av.x; As[ak + 1][arow] = av.y;
        As[ak + 2][arow] = av.z; As[ak + 3][arow] = av.w;
        *(float4*)(&Bs[bk][bn]) = bv;
        __syncthreads();
#pragma unroll
        for (int k = 0; k < 16; k++) {
            float4 a = *(const float4*)(&As[k][ty * 4]);
            float4 b = *(const float4*)(&Bs[k][tx * 4]);
            float ar[4] = {a.x, a.y, a.z, a.w};
            float br[4] = {b.x, b.y, b.z, b.w};
#pragma unroll
            for (int i = 0; i < 4; i++)
#pragma unroll
                for (int j = 0; j < 4; j++) acc[i][j] += ar[i] * br[j];
        }
    }
#pragma unroll
    for (int i = 0; i < 4; i++)
#pragma unroll
        for (int j = 0; j < 4; j++)
            g_Wc[(m0 + ty * 4 + i) * 1024 + (n0 + tx * 4 + j)] = acc[i][j];
}

// ---------------- rs[e] = sum_o Wmap[e,o];  q[e] = Wmap[e,:]@b_lin + b_map[e] ----
__global__ void __launch_bounds__(256) precompute_q_rs(
    const float* __restrict__ Wmap, const float* __restrict__ blin,
    const float* __restrict__ bmap)
{
    const int e = blockIdx.x;
    const int tid = threadIdx.x;
    float rs = 0.f, p = 0.f;
    for (int o = tid; o < 1024; o += 256) {
        float w = Wmap[e * 1024 + o];
        rs += w; p += w * blin[o];
    }
#pragma unroll
    for (int off = 16; off; off >>= 1) {
        rs += __shfl_xor_sync(0xffffffffu, rs, off);
        p  += __shfl_xor_sync(0xffffffffu, p, off);
    }
    __shared__ float srs[8], sp[8];
    if ((tid & 31) == 0) { srs[tid >> 5] = rs; sp[tid >> 5] = p; }
    __syncthreads();
    if (tid == 0) {
        float R = 0.f, P = 0.f;
        for (int i = 0; i < 8; i++) { R += srs[i]; P += sp[i]; }
        g_rs[e] = R;
        g_q[e] = P + bmap[e];
    }
}

// ---------------- u[g'] = W_e[g',:]@rs ; v[g'] = W_e[g',:]@q ----------------
__global__ void __launch_bounds__(256) precompute_uv(const float* __restrict__ W1)
{
    const int wid = threadIdx.x >> 5, lane = threadIdx.x & 31;
    const int gp = blockIdx.x * 8 + wid;          // 0..3071
    const int gate = gp >> 10, h = gp & 1023;
    const int orig = gate_row(gate, h);
    const float* w = W1 + orig * 1280 + 1024;
    float us = 0.f, vs = 0.f;
    for (int e = lane; e < EEMB; e += 32) {
        float ww = w[e];
        us += ww * g_rs[e];
        vs += ww * g_q[e];
    }
#pragma unroll
    for (int off = 16; off; off >>= 1) {
        us += __shfl_xor_sync(0xffffffffu, us, off);
        vs += __shfl_xor_sync(0xffffffffu, vs, off);
    }
    if (lane == 0) { g_u[gp] = us; g_v[gp] = vs; }
}

// ---------------- persistent sequential kernel ----------------
#define SM_W2    0                     // [24][1024]  W_ih2 slices (u*3+gate rows)
#define SM_WE    24576                 // [24][256]   W_e slices
#define SM_WL    30720                 // [8][1024]   W_lin rows
#define SM_WC    38912                 // [2][1024]   Wc rows
#define SM_VEC   40960                 // [1024]      h1/h2 staging
#define SM_E0    41984                 // [256]
#define SM_RED   42240                 // [128]       psum staging
#define SM_GATE  42368                 // [24]
#define SM_B2    42392                 // [24]
#define SM_U     42416                 // [24]
#define SM_V     42440                 // [24]
#define SM_BL    42464                 // [8]
#define SM_PRE   42472                 // [24]
#define SM_MISC  42496                 // [8]
#define SMEM_FLOATS 42504
#define SMEM_BYTES  (SMEM_FLOATS * 4)

__global__ void __launch_bounds__(NT, 1) lstm_seq(
    const float* __restrict__ W_ih1, const float* __restrict__ W_ih2,
    const float* __restrict__ b_ih2, const float* __restrict__ b_hh2,
    const float* __restrict__ W_lin, const float* __restrict__ b_lin,
    float* __restrict__ out)
{
    extern __shared__ float sm[];
    float* sW2   = sm + SM_W2;
    float* sWe   = sm + SM_WE;
    float* sWl   = sm + SM_WL;
    float* sWc   = sm + SM_WC;
    float* sVec  = sm + SM_VEC;
    float* sE0   = sm + SM_E0;
    float* sRed  = sm + SM_RED;
    float* sGate = sm + SM_GATE;
    float* sB2   = sm + SM_B2;
    float* sU    = sm + SM_U;
    float* sV    = sm + SM_V;
    float* sBl   = sm + SM_BL;
    float* sPre  = sm + SM_PRE;
    float* sMisc = sm + SM_MISC;

    const int b = blockIdx.x;
    const int tid = threadIdx.x;
    const int wid = tid >> 5, lane = tid & 31;
    const int h0 = b * 8;                 // this CTA owns hidden units h0..h0+7
    unsigned target = 0;

    // -------- load weight slices into SMEM --------
    for (int idx = tid; idx < 24 * 1024; idx += NT) {
        int j = idx >> 10, k = idx & 1023;            // j = u*3 + gate
        int orig = gate_row(j % 3, h0 + j / 3);
        sW2[idx] = W_ih2[orig * 1024 + k];
    }
    for (int idx = tid; idx < 24 * 256; idx += NT) {
        int j = idx >> 8, e = idx & 255;
        int orig = gate_row(j % 3, h0 + j / 3);
        sWe[idx] = W_ih1[orig * 1280 + 1024 + e];
    }
    for (int idx = tid; idx < 8 * 1024; idx += NT) {
        int r = idx >> 10, k = idx & 1023;
        sWl[idx] = W_lin[(h0 + r) * 1024 + k];
    }
    for (int idx = tid; idx < 2 * 1024; idx += NT) {
        int r = idx >> 10, k = idx & 1023;
        sWc[idx] = g_Wc[(b * 2 + r) * 1024 + k];
    }
    if (tid < 24) {
        int j = tid;
        int orig = gate_row(j % 3, h0 + j / 3);
        sB2[j] = b_ih2[orig] + b_hh2[orig];
        int gp = (j % 3) * 1024 + h0 + j / 3;
        sU[j] = g_u[gp];
        sV[j] = g_v[gp];
        sPre[j] = g_pre[(j % 3) * 1024 + h0 + j / 3];   // t = 0 prefetch
    } else if (tid < 32) {
        sBl[tid - 24] = b_lin[h0 + tid - 24];
    }
    target += NB; grid_bar(target);

    for (int t = 0; t < T; ++t) {
        // ================= Phase A: g1 = pre + W_e@e0 + v - lse*u ; h1 ==========
        if (t > 0) {
            if (tid < 256) sE0[tid] = g_e0[tid];
            else if (tid < 384) sRed[tid - 256] = g_psum[tid - 256];
        }
        __syncthreads();
        float acc = 0.f;
        if (wid < 24 && t > 0) {
            const float4* w4 = (const float4*)(sWe + (wid << 8));
            const float4* e4 = (const float4*)sE0;
#pragma unroll
            for (int i = 0; i < 2; i++) {
                float4 a = w4[lane + 32 * i];
                float4 x = e4[lane + 32 * i];
                acc += a.x * x.x + a.y * x.y + a.z * x.z + a.w * x.w;
            }
#pragma unroll
            for (int off = 16; off; off >>= 1)
                acc += __shfl_xor_sync(0xffffffffu, acc, off);
        }
        if (wid == 24 && t > 0) {
            float s = sRed[lane] + sRed[lane + 32] + sRed[lane + 64] + sRed[lane + 96];
#pragma unroll
            for (int off = 16; off; off >>= 1)
                s += __shfl_xor_sync(0xffffffffu, s, off);
            if (lane == 0) sMisc[0] = logf(s);
        }
        __syncthreads();
        if (wid < 24 && lane == 0) {
            float g1 = sPre[wid];
            if (t > 0) g1 += acc + sV[wid] - sMisc[0] * sU[wid];
            sGate[wid] = g1;
        }
        __syncthreads();
        if (tid < 8) {
            float gi = sGate[tid * 3 + 0];
            float gg = sGate[tid * 3 + 1];
            float go = sGate[tid * 3 + 2];
            float c = sigf(gi) * tanhf(gg);
            g_h1[h0 + tid] = sigf(go) * tanhf(c);
        }
        target += NB; grid_bar(target);

        // ================= Phase B: g2 = W_ih2@h1 + b2 ; h2 =====================
        sVec[tid] = g_h1[tid];
        __syncthreads();
        if (wid < 24) {
            const float4* w4 = (const float4*)(sW2 + (wid << 10));
            const float4* x4 = (const float4*)sVec;
            float a2 = 0.f;
#pragma unroll
            for (int i = 0; i < 8; i++) {
                float4 a = w4[lane + 32 * i];
                float4 x = x4[lane + 32 * i];
                a2 += a.x * x.x + a.y * x.y + a.z * x.z + a.w * x.w;
            }
#pragma unroll
            for (int off = 16; off; off >>= 1)
                a2 += __shfl_xor_sync(0xffffffffu, a2, off);
            if (lane == 0) sGate[wid] = a2 + sB2[wid];
        }
        __syncthreads();
        if (tid < 8) {
            float gi = sGate[tid * 3 + 0];
            float gg = sGate[tid * 3 + 1];
            float go = sGate[tid * 3 + 2];
            float c = sigf(gi) * tanhf(gg);
            g_h2[h0 + tid] = sigf(go) * tanhf(c);
        }
        target += NB; grid_bar(target);

        // ================= Phase C: y, e0 = Wc@h2, expsum partial ===============
        sVec[tid] = g_h2[tid];
        if (t + 1 < T && tid >= 512 && tid < 536) {
            int j = tid - 512;
            sPre[j] = g_pre[(t + 1) * G3 + (j % 3) * 1024 + h0 + j / 3];
        }
        __syncthreads();
        if (wid < 8) {
            const float4* w4 = (const float4*)(sWl + (wid << 10));
            const float4* x4 = (const float4*)sVec;
            float a2 = 0.f;
#pragma unroll
            for (int i = 0; i < 8; i++) {
                float4 a = w4[lane + 32 * i];
                float4 x = x4[lane + 32 * i];
                a2 += a.x * x.x + a.y * x.y + a.z * x.z + a.w * x.w;
            }
#pragma unroll
            for (int off = 16; off; off >>= 1)
                a2 += __shfl_xor_sync(0xffffffffu, a2, off);
            if (lane == 0) {
                float y = a2 + sBl[wid];
                out[t * 1024 + h0 + wid] = y;
                sGate[wid] = expf(y);
            }
        } else if (wid < 10) {
            const int r = wid - 8;
            const float4* w4 = (const float4*)(sWc + (r << 10));
            const float4* x4 = (const float4*)sVec;
            float a2 = 0.f;
#pragma unroll
            for (int i = 0; i < 8; i++) {
                float4 a = w4[lane + 32 * i];
                float4 x = x4[lane + 32 * i];
                a2 += a.x * x.x + a.y * x.y + a.z * x.z + a.w * x.w;
            }
#pragma unroll
            for (int off = 16; off; off >>= 1)
                a2 += __shfl_xor_sync(0xffffffffu, a2, off);
            if (lane == 0) g_e0[b * 2 + r] = a2;
        }
        __syncthreads();
        if (tid == 0) {
            float s = 0.f;
#pragma unroll
            for (int i = 0; i < 8; i++) s += sGate[i];
            g_psum[b] = s;       // fixed order -> deterministic
        }
        target += NB; grid_bar(target);
    }
}

// ---------------- launch ----------------
extern "C" void kernel_launch(void* const* d_in, const int* in_sizes, int n_in,
                              void* d_out, int out_size)
{
    const float* x    = (const float*)d_in[0];
    const float* Wih1 = (const float*)d_in[1];
    const float* bih1 = (const float*)d_in[3];
    const float* bhh1 = (const float*)d_in[4];
    const float* Wih2 = (const float*)d_in[5];
    const float* bih2 = (const float*)d_in[7];
    const float* bhh2 = (const float*)d_in[8];
    const float* Wlin = (const float*)d_in[9];
    const float* blin = (const float*)d_in[10];
    const float* Wmap = (const float*)d_in[11];
    const float* bmap = (const float*)d_in[12];
    float* out = (float*)d_out;

    cudaFuncSetAttribute(lstm_seq, cudaFuncAttributeMaxDynamicSharedMemorySize,
                         SMEM_BYTES);

    init_sync<<<1, 1>>>();
    pre_gemm<<<dim3(G3 / 128, T / 128), 256>>>(x, Wih1, bih1, bhh1);
    wc_gemm<<<dim3(1024 / 64, 256 / 64), 256>>>(Wmap, Wlin);
    precompute_q_rs<<<256, 256>>>(Wmap, blin, bmap);
    precompute_uv<<<G3 / 8, 256>>>(Wih1);
    lstm_seq<<<NB, NT, SMEM_BYTES>>>(Wih1, Wih2, bih2, bhh2, Wlin, blin, out);
}